// round 1
// baseline (speedup 1.0000x reference)
#include <cuda_runtime.h>
#include <math.h>

#define BB 2
#define TT 2048
#define DIMM 1024
#define HH 16
#define DHH 64
#define DTT 32
#define MM (BB*TT)   /* 4096 rows */
#define EPSF 1.1920928955078125e-07f

// ---------------- scratch (no allocation allowed) ----------------
__device__ float g_x[MM * DIMM];        // RMSNormed input
__device__ float g_kv[MM * DIMM];       // softmax(k)*v, layout [b*T + l][h*64 + d]
__device__ float g_P[BB * HH * 64 * 64];// stage-A result [b][h][jj][d]
__device__ float g_load[MM * DIMM];     // loading, layout [b*T + t][h*64 + d]

// Accurate-under-fast-math sincos: reduce in double (value identical to the
// fp32 angle the reference feeds to cos/sin), then sincosf on a small arg.
__device__ __forceinline__ void sincos_acc(float ang, float* s, float* c) {
    const double TWO_PI = 6.283185307179586476925286766559;
    double da = (double)ang;
    da -= floor(da * (1.0 / TWO_PI)) * TWO_PI;   // [0, 2pi)
    sincosf((float)da, s, c);
}

// ---------------- K1: RMSNorm ----------------
__global__ void k_rmsnorm(const float* __restrict__ states, const float* __restrict__ lnw) {
    int row = blockIdx.x;
    int tid = threadIdx.x;                 // 256 threads, 4 floats each
    const float4* src = reinterpret_cast<const float4*>(states + (size_t)row * DIMM);
    float4 v = src[tid];
    float ss = v.x * v.x + v.y * v.y + v.z * v.z + v.w * v.w;
    #pragma unroll
    for (int o = 16; o > 0; o >>= 1) ss += __shfl_xor_sync(0xffffffffu, ss, o);
    __shared__ float wsum[8];
    if ((tid & 31) == 0) wsum[tid >> 5] = ss;
    __syncthreads();
    if (tid < 8) {
        float s2 = wsum[tid];
        #pragma unroll
        for (int o = 4; o > 0; o >>= 1) s2 += __shfl_xor_sync(0xffu, s2, o);
        if (tid == 0) wsum[0] = s2;
    }
    __syncthreads();
    float scale = rsqrtf(wsum[0] * (1.0f / DIMM) + EPSF);
    float4 w = reinterpret_cast<const float4*>(lnw)[tid];
    float4 o;
    o.x = v.x * scale * w.x; o.y = v.y * scale * w.y;
    o.z = v.z * scale * w.z; o.w = v.w * scale * w.w;
    reinterpret_cast<float4*>(g_x + (size_t)row * DIMM)[tid] = o;
}

// ---------------- K2: fused K+V GEMM, per-head softmax, kv = p*v ----------------
// Block: 64 rows x one head (64 cols) for BOTH Wk and Wv. 256 threads, 4x4 micro-tiles.
__global__ void k_kv(const float* __restrict__ Wk, const float* __restrict__ bk,
                     const float* __restrict__ Wv, const float* __restrict__ bv,
                     const int* __restrict__ mask) {
    const int rowBase = blockIdx.x * 64;
    const int hbase   = blockIdx.y * 64;
    const int tid = threadIdx.x;
    const int tx = tid & 15, ty = tid >> 4;

    __shared__ float As[16][64];
    __shared__ float Bks[16][64];
    __shared__ float Bvs[16][64];
    __shared__ float Sk[64][65];
    __shared__ float Sv[64][65];

    float acck[4][4] = {}, accv[4][4] = {};
    const int lr = tid >> 2, lk = (tid & 3) * 4;   // each thread: one float4 per tile

    for (int kt = 0; kt < DIMM; kt += 16) {
        float4 a  = *(const float4*)(g_x + (size_t)(rowBase + lr) * DIMM + kt + lk);
        float4 wk = *(const float4*)(Wk  + (size_t)(hbase  + lr) * DIMM + kt + lk);
        float4 wv = *(const float4*)(Wv  + (size_t)(hbase  + lr) * DIMM + kt + lk);
        As[lk+0][lr]=a.x;  As[lk+1][lr]=a.y;  As[lk+2][lr]=a.z;  As[lk+3][lr]=a.w;
        Bks[lk+0][lr]=wk.x;Bks[lk+1][lr]=wk.y;Bks[lk+2][lr]=wk.z;Bks[lk+3][lr]=wk.w;
        Bvs[lk+0][lr]=wv.x;Bvs[lk+1][lr]=wv.y;Bvs[lk+2][lr]=wv.z;Bvs[lk+3][lr]=wv.w;
        __syncthreads();
        #pragma unroll
        for (int kk = 0; kk < 16; kk++) {
            float4 a4 = *(const float4*)&As[kk][ty * 4];
            float4 k4 = *(const float4*)&Bks[kk][tx * 4];
            float4 v4 = *(const float4*)&Bvs[kk][tx * 4];
            float av[4] = {a4.x, a4.y, a4.z, a4.w};
            float kf[4] = {k4.x, k4.y, k4.z, k4.w};
            float vf[4] = {v4.x, v4.y, v4.z, v4.w};
            #pragma unroll
            for (int i = 0; i < 4; i++)
                #pragma unroll
                for (int j = 0; j < 4; j++) {
                    acck[i][j] += av[i] * kf[j];
                    accv[i][j] += av[i] * vf[j];
                }
        }
        __syncthreads();
    }

    // add biases, stage into smem
    float kb[4], vb[4];
    #pragma unroll
    for (int j = 0; j < 4; j++) { kb[j] = bk[hbase + tx*4 + j]; vb[j] = bv[hbase + tx*4 + j]; }
    #pragma unroll
    for (int i = 0; i < 4; i++)
        #pragma unroll
        for (int j = 0; j < 4; j++) {
            Sk[ty*4+i][tx*4+j] = acck[i][j] + kb[j];
            Sv[ty*4+i][tx*4+j] = accv[i][j] + vb[j];
        }
    __syncthreads();

    // per-row softmax over 64 head dims, then kv = p * v  (thread per row)
    if (tid < 64) {
        int row = rowBase + tid;
        float mval = (float)mask[row];
        float mx = -INFINITY;
        #pragma unroll 8
        for (int c = 0; c < 64; c++) { float l = Sk[tid][c] * mval; mx = fmaxf(mx, l); }
        float sum = 0.0f;
        #pragma unroll 8
        for (int c = 0; c < 64; c++) {
            float e = expf(Sk[tid][c] * mval - mx);
            Sk[tid][c] = e; sum += e;
        }
        float inv = 1.0f / sum;
        #pragma unroll 8
        for (int c = 0; c < 64; c++) Sk[tid][c] = Sk[tid][c] * inv * Sv[tid][c];
    }
    __syncthreads();

    // coalesced writeback
    for (int e = tid; e < 64 * 64; e += 256) {
        int r = e >> 6, c = e & 63;
        g_kv[(size_t)(rowBase + r) * DIMM + hbase + c] = Sk[r][c];
    }
}

// ---------------- K3a: zero P ----------------
__global__ void k_zeroP() {
    int i = blockIdx.x * blockDim.x + threadIdx.x;
    if (i < BB * HH * 64 * 64) g_P[i] = 0.0f;
}

// ---------------- K3: stage A:  P[b,h,jj,d] = sum_l F[l,jj] * kv[b,l,h,d] ----------------
// grid (bh=32, split=8); each block covers 256 l, atomicAdds its 64x64 partial.
__global__ void k_stageA(const float* __restrict__ angles) {
    const int bh = blockIdx.x;            // b*16 + h
    const int b = bh >> 4, h = bh & 15;
    const int lbase0 = blockIdx.y * 256;
    const int tid = threadIdx.x;
    const int tx = tid & 15, ty = tid >> 4;

    __shared__ float F[16][64];
    __shared__ float KVs[16][64];
    __shared__ float wsh[32];
    if (tid < 32) wsh[tid] = angles[tid];
    __syncthreads();

    float acc[4][4] = {};
    for (int sub = 0; sub < 16; sub++) {
        int lbase = lbase0 + sub * 16;
        // 512 sincos per subtile -> 2 per thread
        {
            int e = tid;       int ll = e >> 5, j = e & 31;
            float s, c; sincos_acc((float)(lbase + ll) * wsh[j], &s, &c);
            F[ll][j] = c; F[ll][32 + j] = s;
            e = tid + 256;     ll = e >> 5; j = e & 31;
            sincos_acc((float)(lbase + ll) * wsh[j], &s, &c);
            F[ll][j] = c; F[ll][32 + j] = s;
        }
        int ll2 = tid >> 4, d0 = (tid & 15) * 4;
        *(float4*)&KVs[ll2][d0] =
            *(const float4*)(g_kv + (size_t)(b * TT + lbase + ll2) * DIMM + h * DHH + d0);
        __syncthreads();
        #pragma unroll
        for (int l = 0; l < 16; l++) {
            float4 f4 = *(const float4*)&F[l][ty * 4];
            float4 k4 = *(const float4*)&KVs[l][tx * 4];
            float ff[4] = {f4.x, f4.y, f4.z, f4.w};
            float kk[4] = {k4.x, k4.y, k4.z, k4.w};
            #pragma unroll
            for (int i = 0; i < 4; i++)
                #pragma unroll
                for (int j = 0; j < 4; j++) acc[i][j] += ff[i] * kk[j];
        }
        __syncthreads();
    }
    float* Pp = g_P + (size_t)bh * 64 * 64;
    #pragma unroll
    for (int i = 0; i < 4; i++)
        #pragma unroll
        for (int j = 0; j < 4; j++)
            atomicAdd(&Pp[(ty*4 + i) * 64 + tx*4 + j], acc[i][j]);
}

// ---------------- K4: stage B: loading[b,t,h,d] = sum_jj G[t,h,jj] * P[b,h,jj,d] ----------------
// grid = M/32 blocks; each block: 32 t-rows, loop over 16 heads.
__global__ void k_stageB(const float* __restrict__ angles, const float* __restrict__ hdelta) {
    const int base = blockIdx.x * 32;     // global row = b*T + t
    const int b = base / TT;
    const int tid = threadIdx.x;
    const int tx = tid & 15, ty = tid >> 4;

    __shared__ float Ph[64][64];
    __shared__ float Gs[32][65];
    __shared__ float wsh[32];
    if (tid < 32) wsh[tid] = angles[tid];
    __syncthreads();

    for (int h = 0; h < HH; h++) {
        float dh = hdelta[h];
        for (int e = tid; e < 32 * 32; e += 256) {
            int tl = e >> 5, j = e & 31;
            int trow = base + tl - b * TT;
            float s, c; sincos_acc(((float)trow + dh) * wsh[j], &s, &c);
            Gs[tl][j]      = c * (1.0f / 32.0f);
            Gs[tl][32 + j] = s * (1.0f / 32.0f);
        }
        const float4* Psrc = (const float4*)(g_P + (size_t)(b * HH + h) * 64 * 64);
        float4* Pd = (float4*)Ph;
        for (int e = tid; e < 1024; e += 256) Pd[e] = Psrc[e];
        __syncthreads();

        float acc[2][4] = {};
        #pragma unroll
        for (int jj = 0; jj < 64; jj++) {
            float g0 = Gs[ty*2 + 0][jj];
            float g1 = Gs[ty*2 + 1][jj];
            float4 p = *(const float4*)&Ph[jj][tx * 4];
            acc[0][0] += g0*p.x; acc[0][1] += g0*p.y; acc[0][2] += g0*p.z; acc[0][3] += g0*p.w;
            acc[1][0] += g1*p.x; acc[1][1] += g1*p.y; acc[1][2] += g1*p.z; acc[1][3] += g1*p.w;
        }
        #pragma unroll
        for (int i = 0; i < 2; i++) {
            int row = base + ty*2 + i;
            float4 o = make_float4(acc[i][0], acc[i][1], acc[i][2], acc[i][3]);
            *(float4*)(g_load + (size_t)row * DIMM + h * DHH + tx * 4) = o;
        }
        __syncthreads();
    }
}

// ---------------- K5: output GEMM: out = loading @ Wo^T + bo ----------------
__global__ void k_out(const float* __restrict__ Wo, const float* __restrict__ bo,
                      float* __restrict__ out) {
    const int rowBase = blockIdx.x * 64;
    const int colBase = blockIdx.y * 64;
    const int tid = threadIdx.x;
    const int tx = tid & 15, ty = tid >> 4;

    __shared__ float As[16][64];
    __shared__ float Bs[16][64];
    float acc[4][4] = {};
    const int lr = tid >> 2, lk = (tid & 3) * 4;

    for (int kt = 0; kt < DIMM; kt += 16) {
        float4 a = *(const float4*)(g_load + (size_t)(rowBase + lr) * DIMM + kt + lk);
        float4 w = *(const float4*)(Wo     + (size_t)(colBase + lr) * DIMM + kt + lk);
        As[lk+0][lr]=a.x; As[lk+1][lr]=a.y; As[lk+2][lr]=a.z; As[lk+3][lr]=a.w;
        Bs[lk+0][lr]=w.x; Bs[lk+1][lr]=w.y; Bs[lk+2][lr]=w.z; Bs[lk+3][lr]=w.w;
        __syncthreads();
        #pragma unroll
        for (int kk = 0; kk < 16; kk++) {
            float4 a4 = *(const float4*)&As[kk][ty * 4];
            float4 b4 = *(const float4*)&Bs[kk][tx * 4];
            float av[4] = {a4.x, a4.y, a4.z, a4.w};
            float bv_[4] = {b4.x, b4.y, b4.z, b4.w};
            #pragma unroll
            for (int i = 0; i < 4; i++)
                #pragma unroll
                for (int j = 0; j < 4; j++) acc[i][j] += av[i] * bv_[j];
        }
        __syncthreads();
    }
    float4 bias = *(const float4*)(bo + colBase + tx * 4);
    #pragma unroll
    for (int i = 0; i < 4; i++) {
        float4 o = make_float4(acc[i][0] + bias.x, acc[i][1] + bias.y,
                               acc[i][2] + bias.z, acc[i][3] + bias.w);
        *(float4*)(out + (size_t)(rowBase + ty*4 + i) * DIMM + colBase + tx * 4) = o;
    }
}

// ---------------- launch ----------------
extern "C" void kernel_launch(void* const* d_in, const int* in_sizes, int n_in,
                              void* d_out, int out_size) {
    const float* states = (const float*)d_in[0];
    const int*   mask   = (const int*)  d_in[1];
    const float* lnw    = (const float*)d_in[2];
    const float* angles = (const float*)d_in[3];
    const float* hdelta = (const float*)d_in[4];
    // d_in[5] = Wq, d_in[6] = q_bias : mathematically dead (softmax row-sum == 1)
    const float* Wk = (const float*)d_in[7];
    const float* bk = (const float*)d_in[8];
    const float* Wv = (const float*)d_in[9];
    const float* bv = (const float*)d_in[10];
    const float* Wo = (const float*)d_in[11];
    const float* bo = (const float*)d_in[12];
    float* out = (float*)d_out;

    k_rmsnorm<<<MM, 256>>>(states, lnw);

    dim3 g2(MM / 64, HH);
    k_kv<<<g2, 256>>>(Wk, bk, Wv, bv, mask);

    k_zeroP<<<(BB * HH * 64 * 64) / 256, 256>>>();

    dim3 g3(BB * HH, 8);
    k_stageA<<<g3, 256>>>(angles);

    k_stageB<<<MM / 32, 256>>>(angles, hdelta);

    dim3 g5(MM / 64, DIMM / 64);
    k_out<<<g5, 256>>>(Wo, bo, out);
}